// round 2
// baseline (speedup 1.0000x reference)
#include <cuda_runtime.h>
#include <math.h>

// ---------------- problem constants ----------------
#define B4    4
#define C0IN  64
#define C0OUT 192
#define C1OUT 576
#define HW    96
#define NPIX  (96*96)          // 9216
#define HP    48               // pooled size

// ---------------- scratch (device globals; no allocation allowed) ----------
__device__ float g_y [B4*C0OUT*NPIX];   // after conv0+bn+relu
__device__ float g_t [B4*C0OUT*NPIX];   // branch concat
__device__ float g_t2[B4*C1OUT*NPIX];   // after conv1+bn+relu
__device__ float g_att[B4*192*192];     // attention logits / probs
__device__ float g_o [B4*C0OUT*NPIX];   // attn @ v
__device__ float g_qn[B4*192];          // 1/||q||
__device__ float g_kn[B4*192];          // 1/||k||

// =====================================================================
// Fused 3x3 conv (pad 1) + bias + BN + ReLU.
// Block: 16x16 threads -> 32x32 output tile, 8 output channels per block.
// Each thread computes 2x2 pixels x 8 channels (32 accumulators).
// =====================================================================
__global__ __launch_bounds__(256) void conv3x3_bn_relu(
    const float* __restrict__ in, const float* __restrict__ w,
    const float* __restrict__ bias, const float* __restrict__ gam,
    const float* __restrict__ bet, const float* __restrict__ mu,
    const float* __restrict__ var, float* __restrict__ out,
    int CI, int CO)
{
    __shared__ float sIn[34][34];
    __shared__ float sW[8][9];
    const int tx = threadIdx.x, ty = threadIdx.y;
    const int tid = ty*16 + tx;
    const int cblk = blockIdx.z % (CO >> 3);
    const int b    = blockIdx.z / (CO >> 3);
    const int co0  = cblk * 8;
    const int y0 = blockIdx.y*32, x0 = blockIdx.x*32;

    float acc[8][4];
#pragma unroll
    for (int i = 0; i < 8; i++)
#pragma unroll
        for (int j = 0; j < 4; j++) acc[i][j] = 0.f;

    for (int ci = 0; ci < CI; ci++) {
        __syncthreads();
        const float* ip = in + (size_t)(b*CI + ci) * NPIX;
        for (int l = tid; l < 34*34; l += 256) {
            int i = l / 34, j = l % 34;
            int gy = y0 - 1 + i, gx = x0 - 1 + j;
            float v = 0.f;
            if ((unsigned)gy < 96u && (unsigned)gx < 96u) v = ip[gy*96 + gx];
            ((float*)sIn)[l] = v;
        }
        if (tid < 72)
            ((float*)sW)[tid] = w[((size_t)(co0 + tid/9)*CI + ci)*9 + tid%9];
        __syncthreads();

        float iv[4][4];
#pragma unroll
        for (int r = 0; r < 4; r++)
#pragma unroll
            for (int c = 0; c < 4; c++) iv[r][c] = sIn[2*ty + r][2*tx + c];

#pragma unroll
        for (int co = 0; co < 8; co++) {
#pragma unroll
            for (int ky = 0; ky < 3; ky++)
#pragma unroll
                for (int kx = 0; kx < 3; kx++) {
                    float wv = sW[co][ky*3 + kx];
                    acc[co][0] += iv[ky  ][kx  ] * wv;
                    acc[co][1] += iv[ky  ][kx+1] * wv;
                    acc[co][2] += iv[ky+1][kx  ] * wv;
                    acc[co][3] += iv[ky+1][kx+1] * wv;
                }
        }
    }

    const int oy = y0 + 2*ty, ox = x0 + 2*tx;
#pragma unroll
    for (int co = 0; co < 8; co++) {
        int c = co0 + co;
        float s  = gam[c] * rsqrtf(var[c] + 1e-5f);
        float sh = (bias[c] - mu[c]) * s + bet[c];
        float* op = out + (size_t)(b*CO + c)*NPIX + oy*96 + ox;
        op[0]  = fmaxf(acc[co][0]*s + sh, 0.f);
        op[1]  = fmaxf(acc[co][1]*s + sh, 0.f);
        op[96] = fmaxf(acc[co][2]*s + sh, 0.f);
        op[97] = fmaxf(acc[co][3]*s + sh, 0.f);
    }
}

// =====================================================================
// Branch construction: t[:,0:64]   = bilinear(maxpool2(y[:,0:64]))
//                      t[:,64:128] = y[:,64:128]
//                      t[:,128:192]= bilinear(avgpool2(y[:,128:192]))
// One block per (b, c) plane.
// =====================================================================
__global__ __launch_bounds__(256) void build_t_kernel()
{
    const int z = blockIdx.x;            // 0..767
    const int b = z / 192, c = z % 192;
    const float* yp = g_y + (size_t)(b*192 + c) * NPIX;
    float*       tp = g_t + (size_t)(b*192 + c) * NPIX;
    const int tid = threadIdx.x;

    if (c >= 64 && c < 128) {
        for (int i = tid; i < NPIX; i += 256) tp[i] = yp[i];
        return;
    }
    __shared__ float pool[HP*HP];
    const bool is_max = (c < 64);
    for (int idx = tid; idx < HP*HP; idx += 256) {
        int p = idx / HP, q = idx % HP;
        float a  = yp[(2*p)  *96 + 2*q    ];
        float bb = yp[(2*p)  *96 + 2*q + 1];
        float cc = yp[(2*p+1)*96 + 2*q    ];
        float dd = yp[(2*p+1)*96 + 2*q + 1];
        pool[idx] = is_max ? fmaxf(fmaxf(a,bb), fmaxf(cc,dd))
                           : 0.25f*(a + bb + cc + dd);
    }
    __syncthreads();
    for (int idx = tid; idx < NPIX; idx += 256) {
        int h = idx / 96, w = idx % 96;
        float ch = fminf(fmaxf(0.5f*h - 0.25f, 0.f), 47.f);
        float cw = fminf(fmaxf(0.5f*w - 0.25f, 0.f), 47.f);
        int hlo = (int)ch; int hhi = min(hlo + 1, 47); float hf = ch - hlo;
        int wlo = (int)cw; int whi = min(wlo + 1, 47); float wf = cw - wlo;
        float top = pool[hlo*HP + wlo]*(1.f - wf) + pool[hlo*HP + whi]*wf;
        float bot = pool[hhi*HP + wlo]*(1.f - wf) + pool[hhi*HP + whi]*wf;
        tp[idx] = top*(1.f - hf) + bot*hf;
    }
}

// =====================================================================
// Row L2-norm reciprocals for q (t2 channels 0:192) and k (192:384).
// One block per row; 1536 blocks.
// =====================================================================
__global__ __launch_bounds__(256) void rownorm_kernel()
{
    const int x = blockIdx.x;
    const bool isK = (x >= 768);
    const int r = x % 768;
    const int b = r / 192, c = r % 192;
    const float* p = g_t2 + (size_t)(b*C1OUT + (isK ? 192 : 0) + c) * NPIX;
    const int tid = threadIdx.x;
    float s = 0.f;
    for (int i = tid; i < NPIX; i += 256) { float v = p[i]; s += v*v; }
    __shared__ float sm[256];
    sm[tid] = s; __syncthreads();
    for (int st = 128; st > 0; st >>= 1) {
        if (tid < st) sm[tid] += sm[tid + st];
        __syncthreads();
    }
    if (tid == 0) {
        float inv = 1.f / fmaxf(sqrtf(sm[0]), 1e-12f);
        if (isK) g_kn[r] = inv; else g_qn[r] = inv;
    }
}

// =====================================================================
// S[b,i,j] = temp * qn[i] * kn[j] * sum_n Q[i,n] K[j,n]
// Tile 32x32, K-chunk 32. grid (6,6,4), block 16x16, 2x2 per thread.
// =====================================================================
__global__ __launch_bounds__(256) void qk_gemm_kernel(const float* __restrict__ temp)
{
    __shared__ float Qs[32][33];
    __shared__ float Ks[32][33];
    const int b = blockIdx.z;
    const int i0 = blockIdx.y * 32, j0 = blockIdx.x * 32;
    const float* Q = g_t2 + (size_t)b * C1OUT * NPIX;
    const float* K = Q + (size_t)192 * NPIX;
    const int tx = threadIdx.x, ty = threadIdx.y;
    const int tid = ty*16 + tx;
    float acc[2][2] = {{0.f,0.f},{0.f,0.f}};

    for (int kt = 0; kt < NPIX; kt += 32) {
        __syncthreads();
        for (int l = tid; l < 1024; l += 256) {
            int rr = l >> 5, cc = l & 31;
            Qs[cc][rr] = Q[(size_t)(i0 + rr)*NPIX + kt + cc];
            Ks[cc][rr] = K[(size_t)(j0 + rr)*NPIX + kt + cc];
        }
        __syncthreads();
#pragma unroll
        for (int kk = 0; kk < 32; kk++) {
            float q0 = Qs[kk][2*ty], q1 = Qs[kk][2*ty+1];
            float k0 = Ks[kk][2*tx], k1 = Ks[kk][2*tx+1];
            acc[0][0] += q0*k0; acc[0][1] += q0*k1;
            acc[1][0] += q1*k0; acc[1][1] += q1*k1;
        }
    }
    float tmp = temp[0];
#pragma unroll
    for (int di = 0; di < 2; di++) {
        int i = i0 + 2*ty + di;
        float qs = g_qn[b*192 + i] * tmp;
#pragma unroll
        for (int dj = 0; dj < 2; dj++) {
            int j = j0 + 2*tx + dj;
            g_att[(size_t)(b*192 + i)*192 + j] = acc[di][dj] * qs * g_kn[b*192 + j];
        }
    }
}

// =====================================================================
// Softmax over last dim (192) of g_att. One block per row.
// =====================================================================
__global__ __launch_bounds__(256) void softmax_kernel()
{
    const int row = blockIdx.x;          // 0..767
    float* p = g_att + (size_t)row * 192;
    const int t = threadIdx.x;
    __shared__ float sm[256];
    float v = (t < 192) ? p[t] : -3.0e38f;
    sm[t] = v; __syncthreads();
    for (int s = 128; s > 0; s >>= 1) {
        if (t < s) sm[t] = fmaxf(sm[t], sm[t+s]);
        __syncthreads();
    }
    float mx = sm[0]; __syncthreads();
    float e = (t < 192) ? expf(v - mx) : 0.f;
    sm[t] = e; __syncthreads();
    for (int s = 128; s > 0; s >>= 1) {
        if (t < s) sm[t] += sm[t+s];
        __syncthreads();
    }
    float inv = 1.f / sm[0];
    if (t < 192) p[t] = e * inv;
}

// =====================================================================
// O[b,i,n] = sum_j A[b,i,j] V[b,j,n]   (M=192, K=192, N=9216)
// Tile: 32(M) x 64(N), K-chunk 32. grid (144,6,4), block 16x16,
// each thread 2 rows x 4 cols (float4 smem reads/global writes).
// =====================================================================
__global__ __launch_bounds__(256) void av_gemm_kernel()
{
    __shared__ float As[32][33];
    __shared__ float Vs[32][64];
    const int b = blockIdx.z;
    const int n0 = blockIdx.x * 64, i0 = blockIdx.y * 32;
    const float* A = g_att + (size_t)b * 192 * 192;
    const float* V = g_t2 + (size_t)b * C1OUT * NPIX + (size_t)384 * NPIX;
    const int tx = threadIdx.x, ty = threadIdx.y;
    const int tid = ty*16 + tx;
    float acc[2][4];
#pragma unroll
    for (int i = 0; i < 2; i++)
#pragma unroll
        for (int j = 0; j < 4; j++) acc[i][j] = 0.f;

    for (int kt = 0; kt < 192; kt += 32) {
        __syncthreads();
        for (int l = tid; l < 1024; l += 256) {
            int rr = l >> 5, cc = l & 31;
            As[cc][rr] = A[(size_t)(i0 + rr)*192 + kt + cc];
        }
        for (int l = tid; l < 2048; l += 256) {
            int kk = l >> 6, nn = l & 63;
            Vs[kk][nn] = V[(size_t)(kt + kk)*NPIX + n0 + nn];
        }
        __syncthreads();
#pragma unroll
        for (int kk = 0; kk < 32; kk++) {
            float a0 = As[kk][2*ty], a1 = As[kk][2*ty+1];
            float4 vv = *(const float4*)&Vs[kk][tx*4];
            acc[0][0] += a0*vv.x; acc[0][1] += a0*vv.y;
            acc[0][2] += a0*vv.z; acc[0][3] += a0*vv.w;
            acc[1][0] += a1*vv.x; acc[1][1] += a1*vv.y;
            acc[1][2] += a1*vv.z; acc[1][3] += a1*vv.w;
        }
    }
#pragma unroll
    for (int di = 0; di < 2; di++) {
        float4 o4 = make_float4(acc[di][0], acc[di][1], acc[di][2], acc[di][3]);
        *(float4*)&g_o[(size_t)(b*192 + i0 + 2*ty + di)*NPIX + n0 + tx*4] = o4;
    }
}

// =====================================================================
// Depthwise 3x3 conv (pad 1) + bias on g_o -> d_out.
// grid (3,3,768), block 16x16, 2x2 pixels/thread.
// =====================================================================
__global__ __launch_bounds__(256) void dwconv_kernel(
    const float* __restrict__ w2, const float* __restrict__ b2,
    float* __restrict__ out)
{
    __shared__ float sIn[34][34];
    const int tx = threadIdx.x, ty = threadIdx.y;
    const int tid = ty*16 + tx;
    const int z = blockIdx.z;            // 0..767
    const int b = z / 192, c = z % 192;
    const int y0 = blockIdx.y*32, x0 = blockIdx.x*32;
    const float* ip = g_o + (size_t)(b*192 + c) * NPIX;

    for (int l = tid; l < 34*34; l += 256) {
        int i = l / 34, j = l % 34;
        int gy = y0 - 1 + i, gx = x0 - 1 + j;
        float v = 0.f;
        if ((unsigned)gy < 96u && (unsigned)gx < 96u) v = ip[gy*96 + gx];
        ((float*)sIn)[l] = v;
    }
    __syncthreads();

    float wv[9];
#pragma unroll
    for (int k = 0; k < 9; k++) wv[k] = w2[c*9 + k];
    float bb = b2[c];

    float iv[4][4];
#pragma unroll
    for (int r = 0; r < 4; r++)
#pragma unroll
        for (int cc = 0; cc < 4; cc++) iv[r][cc] = sIn[2*ty + r][2*tx + cc];

    float a00 = bb, a01 = bb, a10 = bb, a11 = bb;
#pragma unroll
    for (int ky = 0; ky < 3; ky++)
#pragma unroll
        for (int kx = 0; kx < 3; kx++) {
            float wk = wv[ky*3 + kx];
            a00 += iv[ky  ][kx  ]*wk;
            a01 += iv[ky  ][kx+1]*wk;
            a10 += iv[ky+1][kx  ]*wk;
            a11 += iv[ky+1][kx+1]*wk;
        }
    const int oy = y0 + 2*ty, ox = x0 + 2*tx;
    float* op = out + (size_t)(b*192 + c)*NPIX + oy*96 + ox;
    op[0] = a00; op[1] = a01; op[96] = a10; op[97] = a11;
}

// =====================================================================
// Launcher
// =====================================================================
extern "C" void kernel_launch(void* const* d_in, const int* in_sizes, int n_in,
                              void* d_out, int out_size)
{
    const float* x    = (const float*)d_in[0];
    const float* w0   = (const float*)d_in[1];
    const float* b0   = (const float*)d_in[2];
    const float* g0   = (const float*)d_in[3];
    const float* be0  = (const float*)d_in[4];
    const float* m0   = (const float*)d_in[5];
    const float* v0   = (const float*)d_in[6];
    const float* w1   = (const float*)d_in[7];
    const float* b1   = (const float*)d_in[8];
    const float* g1   = (const float*)d_in[9];
    const float* be1  = (const float*)d_in[10];
    const float* m1   = (const float*)d_in[11];
    const float* v1   = (const float*)d_in[12];
    const float* temp = (const float*)d_in[13];
    const float* w2   = (const float*)d_in[14];
    const float* b2   = (const float*)d_in[15];
    float* out = (float*)d_out;

    float *py, *pt, *pt2;
    cudaGetSymbolAddress((void**)&py,  g_y);
    cudaGetSymbolAddress((void**)&pt,  g_t);
    cudaGetSymbolAddress((void**)&pt2, g_t2);

    dim3 blk(16, 16);

    // conv0 + bn + relu : x -> g_y
    conv3x3_bn_relu<<<dim3(3, 3, B4 * (C0OUT/8)), blk>>>(
        x, w0, b0, g0, be0, m0, v0, py, C0IN, C0OUT);

    // branches -> g_t
    build_t_kernel<<<B4*192, 256>>>();

    // conv1 + bn + relu : g_t -> g_t2
    conv3x3_bn_relu<<<dim3(3, 3, B4 * (C1OUT/8)), blk>>>(
        pt, w1, b1, g1, be1, m1, v1, pt2, C0OUT, C1OUT);

    // q/k row norms
    rownorm_kernel<<<2*B4*192, 256>>>();

    // attention logits
    qk_gemm_kernel<<<dim3(6, 6, B4), blk>>>(temp);

    // softmax
    softmax_kernel<<<B4*192, 256>>>();

    // attn @ v
    av_gemm_kernel<<<dim3(144, 6, B4), blk>>>();

    // depthwise conv + bias -> output
    dwconv_kernel<<<dim3(3, 3, B4*192), blk>>>(w2, b2, out);
}